// round 3
// baseline (speedup 1.0000x reference)
#include <cuda_runtime.h>
#include <math.h>
#include <stdint.h>

// Problem dims (fixed)
#define NT 2048
#define NB 64
#define NI 256
#define NH 512
#define NG 2048
#define GRID_B 128   // 128 persistent CTAs, 1/SM, single wave
#define NSLICE 16    // k-chunks of 32 rows each
#define KCH 32

// Scratch (__device__ globals; no allocation allowed)
__device__ float g_xw[(size_t)NT * NG * NB];   // [t][col][b]  (transposed vs R1!)
__device__ float g_h[2 * NH * NB];             // [buf][k][b]
__device__ unsigned g_flag[NSLICE * 32];       // per-chunk monotonic counters, padded

__device__ __forceinline__ float sigmoidf_(float x) { return 1.0f / (1.0f + expf(-x)); }

// ---- packed f32x2 helpers ----
__device__ __forceinline__ unsigned long long fma2(unsigned long long a,
                                                   unsigned long long b,
                                                   unsigned long long c) {
    unsigned long long d;
    asm("fma.rn.f32x2 %0, %1, %2, %3;" : "=l"(d) : "l"(a), "l"(b), "l"(c));
    return d;
}
__device__ __forceinline__ unsigned long long add2(unsigned long long a,
                                                   unsigned long long b) {
    unsigned long long d;
    asm("add.rn.f32x2 %0, %1, %2;" : "=l"(d) : "l"(a), "l"(b));
    return d;
}
__device__ __forceinline__ unsigned long long pack2(float x, float y) {
    unsigned long long r;
    asm("mov.b64 %0, {%1, %2};" : "=l"(r) : "f"(x), "f"(y));
    return r;
}
__device__ __forceinline__ float2 unpack2(unsigned long long v) {
    float2 f;
    asm("mov.b64 {%0, %1}, %2;" : "=f"(f.x), "=f"(f.y) : "l"(v));
    return f;
}

__global__ void zero_flags_kernel() {
    if (threadIdx.x < NSLICE) g_flag[threadIdx.x * 32] = 0u;
}

// ---------------- Phase 1: xW = x @ Wi + B, output TRANSPOSED [t][col][b] ----------------
__global__ void __launch_bounds__(256, 2)
xw_gemm_kernel(const float* __restrict__ x, const float* __restrict__ Wi,
               const float* __restrict__ bias) {
    __shared__ __align__(16) float As[8][132];
    __shared__ __align__(16) float Bs[8][128];

    const int tid = threadIdx.x;
    const int tx = tid & 15, ty = tid >> 4;
    const int bm = blockIdx.y << 7, bn = blockIdx.x << 7;
    const int lrow = tid >> 1, lk = (tid & 1) << 2;
    const int brow = tid >> 5, bcol = (tid & 31) << 2;

    unsigned long long acc2[8][4];
    #pragma unroll
    for (int i = 0; i < 8; i++)
        #pragma unroll
        for (int j = 0; j < 4; j++) acc2[i][j] = 0ull;

    for (int kt = 0; kt < NI; kt += 8) {
        float4 av = *reinterpret_cast<const float4*>(x + (size_t)(bm + lrow) * NI + kt + lk);
        float4 bv = *reinterpret_cast<const float4*>(Wi + (size_t)(kt + brow) * NG + bn + bcol);
        As[lk + 0][lrow] = av.x;
        As[lk + 1][lrow] = av.y;
        As[lk + 2][lrow] = av.z;
        As[lk + 3][lrow] = av.w;
        *reinterpret_cast<float4*>(&Bs[brow][bcol]) = bv;
        __syncthreads();
        #pragma unroll
        for (int kk = 0; kk < 8; kk++) {
            float4 t0 = *reinterpret_cast<const float4*>(&As[kk][ty << 3]);
            float4 t1 = *reinterpret_cast<const float4*>(&As[kk][(ty << 3) + 4]);
            const ulonglong2* brow2 = reinterpret_cast<const ulonglong2*>(&Bs[kk][tx << 3]);
            ulonglong2 bv0 = brow2[0], bv1 = brow2[1];
            unsigned long long b2[4] = {bv0.x, bv0.y, bv1.x, bv1.y};
            float a[8] = {t0.x, t0.y, t0.z, t0.w, t1.x, t1.y, t1.z, t1.w};
            #pragma unroll
            for (int i = 0; i < 8; i++) {
                unsigned long long ap = pack2(a[i], a[i]);
                #pragma unroll
                for (int j = 0; j < 4; j++)
                    acc2[i][j] = fma2(ap, b2[j], acc2[i][j]);
            }
        }
        __syncthreads();
    }

    float4 bb0 = *reinterpret_cast<const float4*>(bias + bn + (tx << 3));
    float4 bb1 = *reinterpret_cast<const float4*>(bias + bn + (tx << 3) + 4);
    const float bb[8] = {bb0.x, bb0.y, bb0.z, bb0.w, bb1.x, bb1.y, bb1.z, bb1.w};

    // Transposed store: g_xw[t][col][b], t = row/64, b = row%64.
    const int t_idx = (bm >> 6) + (ty >> 3);
    const int b_base = (ty & 7) << 3;
    float o[8][8];   // [i][j]
    #pragma unroll
    for (int i = 0; i < 8; i++)
        #pragma unroll
        for (int p = 0; p < 4; p++) {
            float2 v = unpack2(acc2[i][p]);
            o[i][2 * p] = v.x + bb[2 * p];
            o[i][2 * p + 1] = v.y + bb[2 * p + 1];
        }
    #pragma unroll
    for (int j = 0; j < 8; j++) {
        int col = bn + (tx << 3) + j;
        float* dst = g_xw + ((size_t)t_idx * NG + col) * NB + b_base;
        *reinterpret_cast<float4*>(dst)     = make_float4(o[0][j], o[1][j], o[2][j], o[3][j]);
        *reinterpret_cast<float4*>(dst + 4) = make_float4(o[4][j], o[5][j], o[6][j], o[7][j]);
    }
}

// ---------------- Phase 2: persistent recurrence, flag-pipelined ----------------
// 128 CTAs x 256 threads. CTA owns units u_base..u_base+3 (16 gate cols).
// Thread (s, cg, bg): k-slice s (32 k), cols 8cg..8cg+7, batches {4bg..+3, 32+4bg..+3}.
// SMEM: dup-Wh 64KB | shT 128KB | sRed 32KB (sGate aliased) = 224KB.
#define SMEM_FLOATS (NH * 32 + NH * NB + 8 * 1024)

__global__ void __launch_bounds__(256, 1)
lstm_rec_kernel(const float* __restrict__ Wh, float* __restrict__ out, int write_state) {
    extern __shared__ float smem[];
    float* sWhD = smem;                   // [512][16 cols x2 duplicated] = 16384 floats
    float* shT  = sWhD + NH * 32;         // [512][64]
    float* sRed = shT + NH * NB;          // [8][16][64]
    float* sGate = sRed;                  // alias (synced)

    const int tid = threadIdx.x;
    const int lane = tid & 31;
    const int u_base = blockIdx.x << 2;
    const int my_chunk = blockIdx.x >> 3;        // chunk this CTA produces

    // Wh, duplicated pairs: sWhD[k*32 + c*2] = sWhD[.. +1] = Wh[k][(c>>2)*512 + u_base + (c&3)]
    for (int idx = tid; idx < NH * 16; idx += 256) {
        int k = idx >> 4, c = idx & 15;
        float w = Wh[(size_t)k * NG + ((c >> 2) * NH) + u_base + (c & 3)];
        sWhD[k * 32 + c * 2] = w;
        sWhD[k * 32 + c * 2 + 1] = w;
    }

    // Zero h buffer 0 (own rows), signal chunk production (flags -> 8 per chunk).
    {
        int ei = tid >> 6, eb = tid & 63;
        __stcg(&g_h[(u_base + ei) * NB + eb], 0.f);
    }
    __syncthreads();
    if (tid == 0) {
        __threadfence();
        atomicAdd(&g_flag[my_chunk * 32], 1u);
    }

    const int bg = tid & 7;
    const int cg = (tid >> 3) & 1;
    const int s  = tid >> 4;               // k-slice 0..15 (half-warp granular)
    const int hl = (lane >> 4);            // half index within warp
    const unsigned half_mask = 0xFFFFu << (hl << 4);
    const int s2 = tid >> 5;               // warp id = slice pair
    const int l16 = tid & 15;              // lane within half

    const int c_loc = tid >> 4;            // reduce: gate-col 0..15
    const int b0 = (tid & 15) << 2;        // reduce: batch base
    const int xw_col = ((c_loc >> 2) * NH) + u_base + (c_loc & 3);

    const int ei = tid >> 6, eb = tid & 63; // cell mapping
    float c_reg = 0.f;

    const unsigned* flagp = &g_flag[s * 32];

    for (int t = 0; t < NT; t++) {
        // Prefetch this thread's xW float4 (hidden behind the matmul).
        float4 xwv = __ldg(reinterpret_cast<const float4*>(
            g_xw + ((size_t)t * NG + xw_col) * NB + b0));

        // Wait for own k-chunk of h[t], then stage it (half-warp local).
        {
            const unsigned target = 8u * (unsigned)(t + 1);
            unsigned v;
            do {
                asm volatile("ld.global.cg.u32 %0, [%1];" : "=r"(v) : "l"(flagp));
                if ((int)(v - target) >= 0) break;
                __nanosleep(40);
            } while (true);
            __threadfence();   // acquire
        }
        {
            const float4* src = reinterpret_cast<const float4*>(
                g_h + (t & 1) * (NH * NB)) + s * 512 + l16;
            float4* dst = reinterpret_cast<float4*>(shT) + s * 512 + l16;
            #pragma unroll
            for (int j = 0; j < 32; j++)
                dst[j * 16] = __ldcg(src + j * 16);
        }
        __syncwarp(half_mask);

        // Matmul over own 32-k slice: acc2[c8][p] = 8 cols x 8 batches (packed pairs)
        unsigned long long acc2[8][4];
        #pragma unroll
        for (int c8 = 0; c8 < 8; c8++)
            #pragma unroll
            for (int p = 0; p < 4; p++) acc2[c8][p] = 0ull;

        const float* wbase = sWhD + (s * KCH) * 32 + cg * 16;
        const float* hbase = shT + s * (KCH * 64) + bg * 4;
        #pragma unroll 4
        for (int kl = 0; kl < KCH; kl++) {
            const ulonglong2* w2 = reinterpret_cast<const ulonglong2*>(wbase + kl * 32);
            ulonglong2 wA = w2[0], wB = w2[1], wC = w2[2], wD = w2[3];
            const ulonglong2* h2 = reinterpret_cast<const ulonglong2*>(hbase + kl * 64);
            ulonglong2 hA = h2[0];   // batches 4bg..4bg+3
            ulonglong2 hB = h2[8];   // batches 32+4bg..32+4bg+3
            unsigned long long wp[8] = {wA.x, wA.y, wB.x, wB.y, wC.x, wC.y, wD.x, wD.y};
            #pragma unroll
            for (int c8 = 0; c8 < 8; c8++) {
                acc2[c8][0] = fma2(wp[c8], hA.x, acc2[c8][0]);
                acc2[c8][1] = fma2(wp[c8], hA.y, acc2[c8][1]);
                acc2[c8][2] = fma2(wp[c8], hB.x, acc2[c8][2]);
                acc2[c8][3] = fma2(wp[c8], hB.y, acc2[c8][3]);
            }
        }

        // Combine slice pairs via shuffle (lane and lane^16 share (cg,bg)).
        __syncwarp();
        #pragma unroll
        for (int c8 = 0; c8 < 8; c8++)
            #pragma unroll
            for (int p = 0; p < 4; p++) {
                unsigned long long other = __shfl_down_sync(0xFFFFFFFFu, acc2[c8][p], 16);
                acc2[c8][p] = add2(acc2[c8][p], other);
            }

        if (lane < 16) {   // lanes of half 0 hold pair sums; write partials
            float* dst = sRed + s2 * 1024 + (cg * 8) * 64 + bg * 4;
            #pragma unroll
            for (int c8 = 0; c8 < 8; c8++) {
                *reinterpret_cast<ulonglong2*>(dst + c8 * 64) =
                    make_ulonglong2(acc2[c8][0], acc2[c8][1]);
                *reinterpret_cast<ulonglong2*>(dst + c8 * 64 + 32) =
                    make_ulonglong2(acc2[c8][2], acc2[c8][3]);
            }
        }
        __syncthreads();   // partials visible

        // Reduce 8 slice-pairs + xW -> gates (regs)
        float4 sum = xwv;
        #pragma unroll
        for (int ss = 0; ss < 8; ss++) {
            float4 v = *reinterpret_cast<const float4*>(sRed + ss * 1024 + c_loc * 64 + b0);
            sum.x += v.x; sum.y += v.y; sum.z += v.z; sum.w += v.w;
        }
        __syncthreads();   // all sRed reads done (sGate aliases sRed)
        *reinterpret_cast<float4*>(sGate + c_loc * 64 + b0) = sum;
        __syncthreads();

        // LSTM cell: thread <-> (unit ei, batch eb)
        {
            float G0 = sGate[((0 * 4 + ei) << 6) + eb];
            float G1 = sGate[((1 * 4 + ei) << 6) + eb];
            float G2 = sGate[((2 * 4 + ei) << 6) + eb];
            float G3 = sGate[((3 * 4 + ei) << 6) + eb];
            float ig = sigmoidf_(G0);
            float fg = sigmoidf_(G1);
            float gg = tanhf(G2);
            float og = sigmoidf_(G3);
            c_reg = fg * c_reg + ig * gg;
            float h = og * tanhf(c_reg);
            int u = u_base + ei;
            out[((size_t)t * NB + eb) * NH + u] = h;
            __stcg(&g_h[((t + 1) & 1) * (NH * NB) + u * NB + eb], h);
            if (write_state && t == NT - 1) {
                size_t base = (size_t)NT * NB * NH;
                out[base + (size_t)eb * NH + u] = h;
                out[base + (size_t)NB * NH + (size_t)eb * NH + u] = c_reg;
            }
        }
        __syncthreads();
        if (tid == 0) {
            __threadfence();   // release h writes (CTA-wide via bar + cumulative fence)
            atomicAdd(&g_flag[my_chunk * 32], 1u);
        }
    }
}

extern "C" void kernel_launch(void* const* d_in, const int* in_sizes, int n_in,
                              void* d_out, int out_size) {
    const float* x  = (const float*)d_in[0];
    const float* Wi = (const float*)d_in[1];
    const float* Wh = (const float*)d_in[2];
    const float* B  = (const float*)d_in[3];
    float* out = (float*)d_out;

    const int smem_bytes = SMEM_FLOATS * (int)sizeof(float);   // 229376 B
    cudaFuncSetAttribute(lstm_rec_kernel, cudaFuncAttributeMaxDynamicSharedMemorySize, smem_bytes);

    zero_flags_kernel<<<1, 32>>>();

    dim3 gA(NG / 128, (NT * NB) / 128);
    xw_gemm_kernel<<<gA, 256>>>(x, Wi, B);

    const long long need_full = (long long)NT * NB * NH + 2LL * NB * NH;
    int write_state = ((long long)out_size >= need_full) ? 1 : 0;

    lstm_rec_kernel<<<GRID_B, 256, smem_bytes>>>(Wh, out, write_state);
}

// round 4
// speedup vs baseline: 2.0412x; 2.0412x over previous
#include <cuda_runtime.h>
#include <math.h>
#include <stdint.h>

// Problem dims (fixed)
#define NT 2048
#define NB 64
#define NI 256
#define NH 512
#define NG 2048
#define GRID_B 128   // 32 unit-groups x 4 batch-groups, 1 CTA/SM, single wave

// Scratch (__device__ globals; no allocation allowed)
__device__ float g_xw[(size_t)NT * NG * NB];   // [t][col][b]  (transposed)
__device__ float g_h[2 * NH * NB];             // [buf][k][b]
__device__ unsigned g_bar_count[4 * 32];       // per batch-group, padded
__device__ unsigned g_bar_gen[4 * 32];

__device__ __forceinline__ float sigmoidf_(float x) { return 1.0f / (1.0f + expf(-x)); }

// ---- packed f32x2 helpers ----
__device__ __forceinline__ unsigned long long fma2(unsigned long long a,
                                                   unsigned long long b,
                                                   unsigned long long c) {
    unsigned long long d;
    asm("fma.rn.f32x2 %0, %1, %2, %3;" : "=l"(d) : "l"(a), "l"(b), "l"(c));
    return d;
}
__device__ __forceinline__ unsigned long long pack2(float x, float y) {
    unsigned long long r;
    asm("mov.b64 %0, {%1, %2};" : "=l"(r) : "f"(x), "f"(y));
    return r;
}
__device__ __forceinline__ float2 unpack2(unsigned long long v) {
    float2 f;
    asm("mov.b64 {%0, %1}, %2;" : "=f"(f.x), "=f"(f.y) : "l"(v));
    return f;
}

// Barrier across the 32 co-resident CTAs of one batch-group (R1-proven pattern).
__device__ __forceinline__ void group_barrier(int grp) {
    __syncthreads();
    if (threadIdx.x == 0) {
        volatile unsigned* genp = &g_bar_gen[grp * 32];
        unsigned my = *genp;
        __threadfence();                       // release: publish h writes
        if (atomicAdd(&g_bar_count[grp * 32], 1u) == 31u) {
            atomicExch(&g_bar_count[grp * 32], 0u);
            __threadfence();
            *genp = my + 1;
        } else {
            while (*genp == my) { __nanosleep(32); }
        }
        __threadfence();                       // acquire
    }
    __syncthreads();
}

// ---------------- Phase 1: xW = x @ Wi + B, output TRANSPOSED [t][col][b] ----------------
__global__ void __launch_bounds__(256, 2)
xw_gemm_kernel(const float* __restrict__ x, const float* __restrict__ Wi,
               const float* __restrict__ bias) {
    __shared__ __align__(16) float As[8][132];
    __shared__ __align__(16) float Bs[8][128];

    const int tid = threadIdx.x;
    const int tx = tid & 15, ty = tid >> 4;
    const int bm = blockIdx.y << 7, bn = blockIdx.x << 7;
    const int lrow = tid >> 1, lk = (tid & 1) << 2;
    const int brow = tid >> 5, bcol = (tid & 31) << 2;

    unsigned long long acc2[8][4];
    #pragma unroll
    for (int i = 0; i < 8; i++)
        #pragma unroll
        for (int j = 0; j < 4; j++) acc2[i][j] = 0ull;

    for (int kt = 0; kt < NI; kt += 8) {
        float4 av = *reinterpret_cast<const float4*>(x + (size_t)(bm + lrow) * NI + kt + lk);
        float4 bv = *reinterpret_cast<const float4*>(Wi + (size_t)(kt + brow) * NG + bn + bcol);
        As[lk + 0][lrow] = av.x;
        As[lk + 1][lrow] = av.y;
        As[lk + 2][lrow] = av.z;
        As[lk + 3][lrow] = av.w;
        *reinterpret_cast<float4*>(&Bs[brow][bcol]) = bv;
        __syncthreads();
        #pragma unroll
        for (int kk = 0; kk < 8; kk++) {
            float4 t0 = *reinterpret_cast<const float4*>(&As[kk][ty << 3]);
            float4 t1 = *reinterpret_cast<const float4*>(&As[kk][(ty << 3) + 4]);
            const ulonglong2* brow2 = reinterpret_cast<const ulonglong2*>(&Bs[kk][tx << 3]);
            ulonglong2 bv0 = brow2[0], bv1 = brow2[1];
            unsigned long long b2[4] = {bv0.x, bv0.y, bv1.x, bv1.y};
            float a[8] = {t0.x, t0.y, t0.z, t0.w, t1.x, t1.y, t1.z, t1.w};
            #pragma unroll
            for (int i = 0; i < 8; i++) {
                unsigned long long ap = pack2(a[i], a[i]);
                #pragma unroll
                for (int j = 0; j < 4; j++)
                    acc2[i][j] = fma2(ap, b2[j], acc2[i][j]);
            }
        }
        __syncthreads();
    }

    float4 bb0 = *reinterpret_cast<const float4*>(bias + bn + (tx << 3));
    float4 bb1 = *reinterpret_cast<const float4*>(bias + bn + (tx << 3) + 4);
    const float bb[8] = {bb0.x, bb0.y, bb0.z, bb0.w, bb1.x, bb1.y, bb1.z, bb1.w};

    // Transposed store: g_xw[t][col][b], t = row/64, b = row%64.
    const int t_idx = (bm >> 6) + (ty >> 3);
    const int b_base = (ty & 7) << 3;
    float o[8][8];
    #pragma unroll
    for (int i = 0; i < 8; i++)
        #pragma unroll
        for (int p = 0; p < 4; p++) {
            float2 v = unpack2(acc2[i][p]);
            o[i][2 * p] = v.x + bb[2 * p];
            o[i][2 * p + 1] = v.y + bb[2 * p + 1];
        }
    #pragma unroll
    for (int j = 0; j < 8; j++) {
        int col = bn + (tx << 3) + j;
        float* dst = g_xw + ((size_t)t_idx * NG + col) * NB + b_base;
        *reinterpret_cast<float4*>(dst)     = make_float4(o[0][j], o[1][j], o[2][j], o[3][j]);
        *reinterpret_cast<float4*>(dst + 4) = make_float4(o[4][j], o[5][j], o[6][j], o[7][j]);
    }
}

// ---------------- Phase 2: persistent recurrence, 2-D partition ----------------
// CTA (ug, bgp): units 16ug..16ug+15 (all 4 gates => 64 cols), batches 16bgp..+15.
// Warp = 64-k slice; lane (cg, bq): cols 8cg..8cg+7, batches 4bq..4bq+3.
// SMEM: sWh [512][64] 128KB | shT [512][16] 32KB | sRed [8][16][64] 32KB = 192KB.
#define SMEM_FLOATS (NH * 64 + NH * 16 + 8 * 16 * 64)

__global__ void __launch_bounds__(256, 1)
lstm_rec_kernel(const float* __restrict__ Wh, float* __restrict__ out, int write_state) {
    extern __shared__ float smem[];
    float* sWh  = smem;                 // [k][c] c = gt*16+u16
    float* shT  = sWh + NH * 64;        // [k][16 batches]
    float* sRed = shT + NH * 16;        // [warp][b16][c]

    const int tid = threadIdx.x;
    const int ug = blockIdx.x >> 2;
    const int bgp = blockIdx.x & 3;

    // Load Wh slice once: c = gt*16+u16 -> global col gt*512 + ug*16 + u16.
    for (int idx = tid; idx < NH * 64; idx += 256) {
        int k = idx >> 6, c = idx & 63;
        int gcol = ((c >> 4) << 9) + (ug << 4) + (c & 15);
        sWh[idx] = Wh[(size_t)k * NG + gcol];
    }
    // Zero own slice of h buffer 0.
    {
        int u = tid & 15, b = tid >> 4;
        g_h[(ug * 16 + u) * NB + bgp * 16 + b] = 0.f;
    }

    const int wrp = tid >> 5;            // k-slice (64 k)
    const int lane = tid & 31;
    const int cg = lane >> 2;            // 8 col-groups
    const int bq = lane & 3;             // 4 batch-quads

    const int u_ = tid & 15, b_ = tid >> 4;   // reduce/cell mapping
    const int hrow = (ug << 4) + u_;
    const int bglob = (bgp << 4) + b_;
    float c_reg = 0.f;

    const float* wbase = sWh + (wrp << 6) * 64 + (cg << 3);
    const float* hbase = shT + (wrp << 6) * 16 + (bq << 2);

    for (int t = 0; t < NT; t++) {
        // Prefetch xW for this step (hidden behind barrier + staging + matmul).
        const float* xwt = g_xw + (size_t)t * ((size_t)NG * NB) + ((ug << 4) + u_) * NB + bglob;
        float xw0 = __ldg(xwt);
        float xw1 = __ldg(xwt + (size_t)(1 << 9) * NB);
        float xw2 = __ldg(xwt + (size_t)(2 << 9) * NB);
        float xw3 = __ldg(xwt + (size_t)(3 << 9) * NB);

        group_barrier(bgp);              // h[t] globally visible for this batch-group

        // Stage own h slice: 512 rows x 16 floats = 32KB.
        {
            const float* src = g_h + (t & 1) * (NH * NB) + (bgp << 4);
            #pragma unroll
            for (int i = 0; i < 8; i++) {
                int idx = tid + (i << 8);
                int row = idx >> 2, part = (idx & 3) << 2;
                float4 v = __ldcg(reinterpret_cast<const float4*>(src + row * NB + part));
                *reinterpret_cast<float4*>(shT + row * 16 + part) = v;
            }
        }
        __syncthreads();

        // Matmul over own 64-k slice: 4 col-pairs x 4 batches, FFMA2.
        unsigned long long acc[4][4];
        #pragma unroll
        for (int cp = 0; cp < 4; cp++)
            #pragma unroll
            for (int bb = 0; bb < 4; bb++) acc[cp][bb] = 0ull;

        #pragma unroll 4
        for (int kl = 0; kl < 64; kl++) {
            ulonglong2 wA = *reinterpret_cast<const ulonglong2*>(wbase + kl * 64);
            ulonglong2 wB = *reinterpret_cast<const ulonglong2*>(wbase + kl * 64 + 4);
            float4 h = *reinterpret_cast<const float4*>(hbase + kl * 16);
            unsigned long long wp[4] = {wA.x, wA.y, wB.x, wB.y};
            unsigned long long hd[4] = {pack2(h.x, h.x), pack2(h.y, h.y),
                                        pack2(h.z, h.z), pack2(h.w, h.w)};
            #pragma unroll
            for (int cp = 0; cp < 4; cp++) {
                acc[cp][0] = fma2(wp[cp], hd[0], acc[cp][0]);
                acc[cp][1] = fma2(wp[cp], hd[1], acc[cp][1]);
                acc[cp][2] = fma2(wp[cp], hd[2], acc[cp][2]);
                acc[cp][3] = fma2(wp[cp], hd[3], acc[cp][3]);
            }
        }

        // Write partials: sRed[wrp][batch][col], 2 STS.128 per batch.
        #pragma unroll
        for (int bb = 0; bb < 4; bb++) {
            float2 p0 = unpack2(acc[0][bb]);
            float2 p1 = unpack2(acc[1][bb]);
            float2 p2 = unpack2(acc[2][bb]);
            float2 p3 = unpack2(acc[3][bb]);
            float* dst = sRed + (wrp << 10) + (((bq << 2) + bb) << 6) + (cg << 3);
            *reinterpret_cast<float4*>(dst)     = make_float4(p0.x, p0.y, p1.x, p1.y);
            *reinterpret_cast<float4*>(dst + 4) = make_float4(p2.x, p2.y, p3.x, p3.y);
        }
        __syncthreads();

        // Reduce 8 warp-partials + xW, then the LSTM cell. Thread <-> (u_, b_).
        {
            float G0 = xw0, G1 = xw1, G2 = xw2, G3 = xw3;
            #pragma unroll
            for (int w = 0; w < 8; w++) {
                const float* rp = sRed + (w << 10) + (b_ << 6) + u_;
                G0 += rp[0];
                G1 += rp[16];
                G2 += rp[32];
                G3 += rp[48];
            }
            float ig = sigmoidf_(G0);
            float fg = sigmoidf_(G1);
            float gg = tanhf(G2);
            float og = sigmoidf_(G3);
            c_reg = fg * c_reg + ig * gg;
            float h = og * tanhf(c_reg);
            out[((size_t)t * NB + bglob) * NH + hrow] = h;
            __stcg(&g_h[((t + 1) & 1) * (NH * NB) + hrow * NB + bglob], h);
            if (write_state && t == NT - 1) {
                size_t base = (size_t)NT * NB * NH;
                out[base + (size_t)bglob * NH + hrow] = h;
                out[base + (size_t)NB * NH + (size_t)bglob * NH + hrow] = c_reg;
            }
        }
        // Next loop-top group_barrier publishes these h writes.
    }
}

extern "C" void kernel_launch(void* const* d_in, const int* in_sizes, int n_in,
                              void* d_out, int out_size) {
    const float* x  = (const float*)d_in[0];
    const float* Wi = (const float*)d_in[1];
    const float* Wh = (const float*)d_in[2];
    const float* B  = (const float*)d_in[3];
    float* out = (float*)d_out;

    const int smem_bytes = SMEM_FLOATS * (int)sizeof(float);   // 196608 B
    cudaFuncSetAttribute(lstm_rec_kernel, cudaFuncAttributeMaxDynamicSharedMemorySize, smem_bytes);

    dim3 gA(NG / 128, (NT * NB) / 128);
    xw_gemm_kernel<<<gA, 256>>>(x, Wi, B);

    const long long need_full = (long long)NT * NB * NH + 2LL * NB * NH;
    int write_state = ((long long)out_size >= need_full) ? 1 : 0;

    lstm_rec_kernel<<<GRID_B, 256, smem_bytes>>>(Wh, out, write_state);
}